// round 5
// baseline (speedup 1.0000x reference)
#include <cuda_runtime.h>
#include <cuda_bf16.h>
#include <cstdint>

// ---------------------------------------------------------------------------
// Dcls1d via mma.sync (HMMA) bf16 split-GEMM.
//   out[b,o,t] = bias[o] + sum_{d,i} K2[d,o,i] * x[b,i,t+d-16]
//   fp32 emulated as bf16 hi+lo, 3 products (hh, hl, lh), fp32 accum.
// R5: R3 math (A staged per d -- K2 varies with d!), 512 threads,
//     1 syncthreads per d, cp.async A(d+1) overlapped with compute(d).
// ---------------------------------------------------------------------------

#define B_   8
#define C_   256
#define T_   2048
#define O_   256
#define DKS_ 33
#define KC_  16
#define TP_  2080   // 16 + 2048 + 16 padded time rows

__device__ __nv_bfloat16 g_Khi[DKS_ * O_ * C_];   // [d][o][i]
__device__ __nv_bfloat16 g_Klo[DKS_ * O_ * C_];
__device__ __nv_bfloat16 g_Xhi[B_ * TP_ * C_];    // [b][t+16][i]
__device__ __nv_bfloat16 g_Xlo[B_ * TP_ * C_];

// ---- PTX helpers -----------------------------------------------------------
__device__ __forceinline__ uint32_t smem_u32(const void* p) {
    uint32_t a;
    asm("{ .reg .u64 t; cvta.to.shared.u64 t, %1; cvt.u32.u64 %0, t; }"
        : "=r"(a) : "l"(p));
    return a;
}
__device__ __forceinline__ void cpa16(uint32_t dst, const void* src) {
    asm volatile("cp.async.ca.shared.global [%0], [%1], 16;" :: "r"(dst), "l"(src));
}
#define CP_COMMIT() asm volatile("cp.async.commit_group;" ::: "memory")
#define CP_WAIT0()  asm volatile("cp.async.wait_group 0;" ::: "memory")

__device__ __forceinline__ void ldmx4(uint32_t* r, uint32_t addr) {
    asm volatile("ldmatrix.sync.aligned.m8n8.x4.shared.b16 {%0,%1,%2,%3}, [%4];"
                 : "=r"(r[0]), "=r"(r[1]), "=r"(r[2]), "=r"(r[3]) : "r"(addr));
}
#define MMA(dv, a, b0v, b1v)                                                   \
    asm volatile("mma.sync.aligned.m16n8k16.row.col.f32.bf16.bf16.f32 "        \
                 "{%0,%1,%2,%3},{%4,%5,%6,%7},{%8,%9},{%0,%1,%2,%3};"          \
                 : "+f"((dv)[0]), "+f"((dv)[1]), "+f"((dv)[2]), "+f"((dv)[3])  \
                 : "r"((a)[0]), "r"((a)[1]), "r"((a)[2]), "r"((a)[3]),         \
                   "r"(b0v), "r"(b1v))

// ---------------------------------------------------------------------------
// Prep 1: build K2 (bf16 hi/lo), layout [d][o][i].
// ---------------------------------------------------------------------------
__global__ void build_k2(const float* __restrict__ w, const float* __restrict__ P) {
    int oi = blockIdx.x * 256 + threadIdx.x;
    int ig = oi & 255;
    float acc[DKS_];
#pragma unroll
    for (int d = 0; d < DKS_; ++d) acc[d] = 0.f;

    const float* Prow  = P + (size_t)oi * KC_;
    const float* P0row = P + (size_t)ig * KC_;    // out-channel 0 (frac source)
    const float* Wrow  = w + (size_t)oi * KC_;
#pragma unroll
    for (int k = 0; k < KC_; ++k) {
        float pp  = Prow[k] + 16.f;
        int   p   = (int)floorf(pp);
        float pp0 = P0row[k] + 16.f;
        float fr  = pp0 - floorf(pp0);
        float wv  = Wrow[k];
        if (p >= 0 && p < DKS_)         acc[p]     += wv * (1.f - fr);
        if (p + 1 >= 0 && p + 1 < DKS_) acc[p + 1] += wv * fr;
    }
#pragma unroll
    for (int d = 0; d < DKS_; ++d) {
        float v = acc[d];
        __nv_bfloat16 h = __float2bfloat16(v);
        __nv_bfloat16 l = __float2bfloat16(v - __bfloat162float(h));
        size_t idx = (size_t)(d * O_ + (oi >> 8)) * C_ + ig;
        g_Khi[idx] = h;
        g_Klo[idx] = l;
    }
}

// ---------------------------------------------------------------------------
// Prep 2: transpose+split x -> g_Xhi/lo [b][t+16][i]
// ---------------------------------------------------------------------------
__global__ void xsplit(const float* __restrict__ x) {
    __shared__ float sm[32][33];
    int t0 = blockIdx.x * 32, i0 = blockIdx.y * 32, b = blockIdx.z;
    int tl = threadIdx.x & 31, th = threadIdx.x >> 5;
#pragma unroll
    for (int k = 0; k < 4; ++k) {
        int i = i0 + th + k * 8;
        sm[th + k * 8][tl] = x[((size_t)b * C_ + i) * T_ + t0 + tl];
    }
    __syncthreads();
#pragma unroll
    for (int k = 0; k < 4; ++k) {
        int t = t0 + th + k * 8;
        float v = sm[tl][th + k * 8];
        __nv_bfloat16 h = __float2bfloat16(v);
        __nv_bfloat16 l = __float2bfloat16(v - __bfloat162float(h));
        size_t idx = ((size_t)b * TP_ + t + 16) * C_ + i0 + tl;
        g_Xhi[idx] = h;
        g_Xlo[idx] = l;
    }
}

__global__ void zpad() {
    int idx = blockIdx.x * 1024 + threadIdx.x;     // 65536 total
    int b = idx >> 13, r = (idx >> 8) & 31, i = idx & 255;
    int row = (r < 16) ? r : (TP_ - 32 + r);
    size_t o = ((size_t)b * TP_ + row) * C_ + i;
    g_Xhi[o] = __float2bfloat16(0.f);
    g_Xlo[o] = __float2bfloat16(0.f);
}

// ---------------------------------------------------------------------------
// Main GEMM kernel.
// Block: 128 o x 128 t, 512 threads (16 warps: 4 M x 4 N, warp = 32 o x 32 t).
// smem rows: 80B stride -> conflict-free ldmatrix without swizzle.
//   A (K2[d] tile): 128 rows x 32 i, hi+lo, double buffered (per-d restage!)
//   X tile:         160 rows x 32 i, hi+lo (per-ic; tap shift = +d rows)
// ---------------------------------------------------------------------------
#define ROWB   80u
#define A_TS   10240u      // one A tensor (128*80)
#define A_BUF  20480u      // hi+lo pair
#define X_OFF  40960u
#define X_TS   12800u      // one X tensor (160*80)
#define DSMEM  (40960u + 25600u + 256u)

__device__ __forceinline__ void stage_A(uint32_t A0, int d, int o0, int ic, int tid) {
    uint32_t Ab = A0 + (uint32_t)(d & 1) * A_BUF;
#pragma unroll
    for (int k = 0; k < 2; ++k) {
        int idx = tid + k * 512;
        int tn  = idx >> 9;
        int r   = (idx >> 2) & 127;
        int c   = idx & 3;
        const __nv_bfloat16* src = (tn ? g_Klo : g_Khi)
            + ((size_t)(d * 256 + o0 + r) * 256 + ic * 32 + c * 8);
        cpa16(Ab + (uint32_t)tn * A_TS + r * ROWB + c * 16, src);
    }
}

__global__ __launch_bounds__(512, 1)
void conv_mma(const float* __restrict__ bias, float* __restrict__ out) {
    extern __shared__ char dsm_raw[];
    uint32_t raw  = smem_u32(dsm_raw);
    uint32_t base = (raw + 127u) & ~127u;

    const int tid  = threadIdx.x;
    const int lane = tid & 31, w = tid >> 5;
    const int wm = w & 3, wn = w >> 2;            // 4 M-warps x 4 N-warps
    const int b  = blockIdx.x >> 4;
    const int t0 = (blockIdx.x & 15) * 128;
    const int o0 = blockIdx.y * 128;

    const uint32_t A0 = base;
    const uint32_t X0 = base + X_OFF;

    float acc[2][4][4];                           // [mi][p*2+nn][quad]
#pragma unroll
    for (int mi = 0; mi < 2; ++mi)
#pragma unroll
        for (int nf = 0; nf < 4; ++nf)
#pragma unroll
            for (int q = 0; q < 4; ++q) acc[mi][nf][q] = 0.f;

    // ldmatrix per-lane row/col offsets
    const uint32_t a_r = (lane & 7) + 8 * ((lane >> 3) & 1);
    const uint32_t a_c = (uint32_t)(lane >> 4) * 16;
    const uint32_t b_r = (lane & 7) + 8 * (lane >> 4);
    const uint32_t b_c = (uint32_t)((lane >> 3) & 1) * 16;

    for (int ic = 0; ic < 8; ++ic) {
        __syncthreads();    // protect X & A buffers vs previous ic's compute
        // ---- stage X tile (160 rows x 32 i, hi+lo): 1280 x 16B chunks ----
#pragma unroll
        for (int k = 0; k < 3; ++k) {
            int idx = tid + k * 512;
            if (idx < 1280) {
                int tn  = idx >= 640;
                int r   = (idx - tn * 640) >> 2;
                int c   = idx & 3;
                const __nv_bfloat16* src = (tn ? g_Xlo : g_Xhi)
                    + ((size_t)(b * TP_ + t0 + r) * 256 + ic * 32 + c * 8);
                cpa16(X0 + (uint32_t)tn * X_TS + r * ROWB + c * 16, src);
            }
        }
        // ---- stage A(d=0) into buf0 ----
        stage_A(A0, 0, o0, ic, tid);
        CP_COMMIT();

#pragma unroll 1
        for (int d = 0; d < DKS_; ++d) {
            CP_WAIT0();        // A(d) (and X on d=0) landed for this thread
            __syncthreads();   // visible to all; everyone done with buf (d+1)&1

            if (d < DKS_ - 1) {            // overlap A(d+1) copy with compute(d)
                stage_A(A0, d + 1, o0, ic, tid);
                CP_COMMIT();
            }

            const uint32_t Ab = A0 + (uint32_t)(d & 1) * A_BUF;
            // ---- A fragments for this d ----
            uint32_t ah[2][2][4], al[2][2][4];    // [kk][mi][4]
#pragma unroll
            for (int kk = 0; kk < 2; ++kk)
#pragma unroll
                for (int mi = 0; mi < 2; ++mi) {
                    uint32_t ad = Ab + (wm * 32 + mi * 16 + a_r) * ROWB + kk * 32 + a_c;
                    ldmx4(ah[kk][mi], ad);
                    ldmx4(al[kk][mi], ad + A_TS);
                }
            // ---- B fragments + MMAs ----
#pragma unroll
            for (int kk = 0; kk < 2; ++kk) {
#pragma unroll
                for (int p = 0; p < 2; ++p) {
                    uint32_t bh[4], bl[4];
                    uint32_t bd = X0 + (wn * 32 + d + p * 16 + b_r) * ROWB
                                + kk * 32 + b_c;
                    ldmx4(bh, bd);
                    ldmx4(bl, bd + X_TS);
#pragma unroll
                    for (int mi = 0; mi < 2; ++mi)
#pragma unroll
                        for (int nn = 0; nn < 2; ++nn) {
                            MMA(acc[mi][p * 2 + nn], ah[kk][mi], bh[2 * nn], bh[2 * nn + 1]);
                            MMA(acc[mi][p * 2 + nn], ah[kk][mi], bl[2 * nn], bl[2 * nn + 1]);
                            MMA(acc[mi][p * 2 + nn], al[kk][mi], bh[2 * nn], bh[2 * nn + 1]);
                        }
                }
            }
        }
    }

    // ---- epilogue: add bias, store float2 ----
    const int g = lane >> 2, tg = lane & 3;
#pragma unroll
    for (int mi = 0; mi < 2; ++mi) {
        int o1 = o0 + wm * 32 + mi * 16 + g;
        float bv1 = bias[o1], bv2 = bias[o1 + 8];
        float* r1 = out + ((size_t)(b * O_ + o1)) * T_ + t0 + wn * 32 + tg * 2;
        float* r2 = r1 + 8 * T_;
#pragma unroll
        for (int nf = 0; nf < 4; ++nf) {
            float2 v1 = make_float2(acc[mi][nf][0] + bv1, acc[mi][nf][1] + bv1);
            float2 v2 = make_float2(acc[mi][nf][2] + bv2, acc[mi][nf][3] + bv2);
            *(float2*)(r1 + nf * 8) = v1;
            *(float2*)(r2 + nf * 8) = v2;
        }
    }
}

// ---------------------------------------------------------------------------
// Launch
// ---------------------------------------------------------------------------
extern "C" void kernel_launch(void* const* d_in, const int* in_sizes, int n_in,
                              void* d_out, int out_size) {
    const float* x      = (const float*)d_in[0];
    const float* weight = (const float*)d_in[1];
    const float* P      = (const float*)d_in[2];
    const float* bias   = (const float*)d_in[3];
    float* out          = (float*)d_out;

    build_k2<<<256, 256>>>(weight, P);
    xsplit<<<dim3(T_ / 32, C_ / 32, B_), 256>>>(x);
    zpad<<<64, 1024>>>();

    cudaFuncSetAttribute(conv_mma, cudaFuncAttributeMaxDynamicSharedMemorySize, DSMEM);
    conv_mma<<<dim3(128, 2), 512, DSMEM>>>(bias, out);
}

// round 6
// speedup vs baseline: 1.9618x; 1.9618x over previous
#include <cuda_runtime.h>
#include <cuda_bf16.h>
#include <cstdint>

// ---------------------------------------------------------------------------
// Dcls1d via mma.sync (HMMA) bf16 split-GEMM.
//   out[b,o,t] = bias[o] + sum_{d,i} K2[d,o,i] * x[b,i,t+d-16]
//   fp32 emulated as bf16 hi+lo, 3 products (hh, hl, lh), fp32 accum.
// R6: block 128o x 256t, 512 threads (16 warps, 4Mx4N, warp=32o x 64t).
//     Single wave (128 blocks). 1 syncthreads/d, A(d+1) copy overlaps compute.
// ---------------------------------------------------------------------------

#define B_   8
#define C_   256
#define T_   2048
#define O_   256
#define DKS_ 33
#define KC_  16
#define TP_  2080   // 16 + 2048 + 16 padded time rows

__device__ __nv_bfloat16 g_Khi[DKS_ * O_ * C_];   // [d][o][i]
__device__ __nv_bfloat16 g_Klo[DKS_ * O_ * C_];
__device__ __nv_bfloat16 g_Xhi[B_ * TP_ * C_];    // [b][t+16][i]
__device__ __nv_bfloat16 g_Xlo[B_ * TP_ * C_];

// ---- PTX helpers -----------------------------------------------------------
__device__ __forceinline__ uint32_t smem_u32(const void* p) {
    uint32_t a;
    asm("{ .reg .u64 t; cvta.to.shared.u64 t, %1; cvt.u32.u64 %0, t; }"
        : "=r"(a) : "l"(p));
    return a;
}
__device__ __forceinline__ void cpa16(uint32_t dst, const void* src) {
    asm volatile("cp.async.ca.shared.global [%0], [%1], 16;" :: "r"(dst), "l"(src));
}
#define CP_COMMIT() asm volatile("cp.async.commit_group;" ::: "memory")
#define CP_WAIT0()  asm volatile("cp.async.wait_group 0;" ::: "memory")

__device__ __forceinline__ void ldmx4(uint32_t* r, uint32_t addr) {
    asm volatile("ldmatrix.sync.aligned.m8n8.x4.shared.b16 {%0,%1,%2,%3}, [%4];"
                 : "=r"(r[0]), "=r"(r[1]), "=r"(r[2]), "=r"(r[3]) : "r"(addr));
}
#define MMA(dv, a, b0v, b1v)                                                   \
    asm volatile("mma.sync.aligned.m16n8k16.row.col.f32.bf16.bf16.f32 "        \
                 "{%0,%1,%2,%3},{%4,%5,%6,%7},{%8,%9},{%0,%1,%2,%3};"          \
                 : "+f"((dv)[0]), "+f"((dv)[1]), "+f"((dv)[2]), "+f"((dv)[3])  \
                 : "r"((a)[0]), "r"((a)[1]), "r"((a)[2]), "r"((a)[3]),         \
                   "r"(b0v), "r"(b1v))

// ---------------------------------------------------------------------------
// Prep 1: build K2 (bf16 hi/lo), layout [d][o][i].
// ---------------------------------------------------------------------------
__global__ void build_k2(const float* __restrict__ w, const float* __restrict__ P) {
    int oi = blockIdx.x * 256 + threadIdx.x;
    int ig = oi & 255;
    float acc[DKS_];
#pragma unroll
    for (int d = 0; d < DKS_; ++d) acc[d] = 0.f;

    const float* Prow  = P + (size_t)oi * KC_;
    const float* P0row = P + (size_t)ig * KC_;    // out-channel 0 (frac source)
    const float* Wrow  = w + (size_t)oi * KC_;
#pragma unroll
    for (int k = 0; k < KC_; ++k) {
        float pp  = Prow[k] + 16.f;
        int   p   = (int)floorf(pp);
        float pp0 = P0row[k] + 16.f;
        float fr  = pp0 - floorf(pp0);
        float wv  = Wrow[k];
        if (p >= 0 && p < DKS_)         acc[p]     += wv * (1.f - fr);
        if (p + 1 >= 0 && p + 1 < DKS_) acc[p + 1] += wv * fr;
    }
#pragma unroll
    for (int d = 0; d < DKS_; ++d) {
        float v = acc[d];
        __nv_bfloat16 h = __float2bfloat16(v);
        __nv_bfloat16 l = __float2bfloat16(v - __bfloat162float(h));
        size_t idx = (size_t)(d * O_ + (oi >> 8)) * C_ + ig;
        g_Khi[idx] = h;
        g_Klo[idx] = l;
    }
}

// ---------------------------------------------------------------------------
// Prep 2: transpose+split x -> g_Xhi/lo [b][t+16][i]
// ---------------------------------------------------------------------------
__global__ void xsplit(const float* __restrict__ x) {
    __shared__ float sm[32][33];
    int t0 = blockIdx.x * 32, i0 = blockIdx.y * 32, b = blockIdx.z;
    int tl = threadIdx.x & 31, th = threadIdx.x >> 5;
#pragma unroll
    for (int k = 0; k < 4; ++k) {
        int i = i0 + th + k * 8;
        sm[th + k * 8][tl] = x[((size_t)b * C_ + i) * T_ + t0 + tl];
    }
    __syncthreads();
#pragma unroll
    for (int k = 0; k < 4; ++k) {
        int t = t0 + th + k * 8;
        float v = sm[tl][th + k * 8];
        __nv_bfloat16 h = __float2bfloat16(v);
        __nv_bfloat16 l = __float2bfloat16(v - __bfloat162float(h));
        size_t idx = ((size_t)b * TP_ + t + 16) * C_ + i0 + tl;
        g_Xhi[idx] = h;
        g_Xlo[idx] = l;
    }
}

__global__ void zpad() {
    int idx = blockIdx.x * 1024 + threadIdx.x;     // 65536 total
    int b = idx >> 13, r = (idx >> 8) & 31, i = idx & 255;
    int row = (r < 16) ? r : (TP_ - 32 + r);
    size_t o = ((size_t)b * TP_ + row) * C_ + i;
    g_Xhi[o] = __float2bfloat16(0.f);
    g_Xlo[o] = __float2bfloat16(0.f);
}

// ---------------------------------------------------------------------------
// Main GEMM kernel.
// Block: 128 o x 256 t, 512 threads (16 warps: 4 M x 4 N, warp = 32 o x 64 t).
// smem rows: 80B stride -> conflict-free ldmatrix without swizzle.
//   A (K2[d] tile): 128 rows x 32 i, hi+lo, double buffered (per-d restage)
//   X tile:         288 rows x 32 i, hi+lo (per-ic; tap shift = +d rows)
// ---------------------------------------------------------------------------
#define ROWB   80u
#define A_TS   10240u      // one A tensor (128*80)
#define A_BUF  20480u      // hi+lo pair
#define X_OFF  40960u
#define X_TS   23040u      // one X tensor (288*80)
#define DSMEM  (40960u + 2u * 23040u + 256u)

__device__ __forceinline__ void stage_A(uint32_t A0, int d, int o0, int ic, int tid) {
    uint32_t Ab = A0 + (uint32_t)(d & 1) * A_BUF;
#pragma unroll
    for (int k = 0; k < 2; ++k) {
        int idx = tid + k * 512;
        int tn  = idx >> 9;
        int r   = (idx >> 2) & 127;
        int c   = idx & 3;
        const __nv_bfloat16* src = (tn ? g_Klo : g_Khi)
            + ((size_t)(d * 256 + o0 + r) * 256 + ic * 32 + c * 8);
        cpa16(Ab + (uint32_t)tn * A_TS + r * ROWB + c * 16, src);
    }
}

__global__ __launch_bounds__(512, 1)
void conv_mma(const float* __restrict__ bias, float* __restrict__ out) {
    extern __shared__ char dsm_raw[];
    uint32_t raw  = smem_u32(dsm_raw);
    uint32_t base = (raw + 127u) & ~127u;

    const int tid  = threadIdx.x;
    const int lane = tid & 31, w = tid >> 5;
    const int wm = w & 3, wn = w >> 2;            // 4 M-warps x 4 N-warps
    const int b  = blockIdx.x >> 3;
    const int t0 = (blockIdx.x & 7) * 256;
    const int o0 = blockIdx.y * 128;

    const uint32_t A0 = base;
    const uint32_t X0 = base + X_OFF;

    float acc[2][8][4];                           // [mi][p*2+nn][quad]
#pragma unroll
    for (int mi = 0; mi < 2; ++mi)
#pragma unroll
        for (int nf = 0; nf < 8; ++nf)
#pragma unroll
            for (int q = 0; q < 4; ++q) acc[mi][nf][q] = 0.f;

    // ldmatrix per-lane row/col offsets
    const uint32_t a_r = (lane & 7) + 8 * ((lane >> 3) & 1);
    const uint32_t a_c = (uint32_t)(lane >> 4) * 16;
    const uint32_t b_r = (lane & 7) + 8 * (lane >> 4);
    const uint32_t b_c = (uint32_t)((lane >> 3) & 1) * 16;

    for (int ic = 0; ic < 8; ++ic) {
        __syncthreads();    // protect X & A buffers vs previous ic's compute
        // ---- stage X tile (288 rows x 32 i, hi+lo): 2304 x 16B chunks ----
#pragma unroll
        for (int k = 0; k < 5; ++k) {
            int idx = tid + k * 512;
            if (idx < 2304) {
                int tn  = idx >= 1152;
                int r   = (idx - tn * 1152) >> 2;
                int c   = idx & 3;
                const __nv_bfloat16* src = (tn ? g_Xlo : g_Xhi)
                    + ((size_t)(b * TP_ + t0 + r) * 256 + ic * 32 + c * 8);
                cpa16(X0 + (uint32_t)tn * X_TS + r * ROWB + c * 16, src);
            }
        }
        // ---- stage A(d=0) into buf0 ----
        stage_A(A0, 0, o0, ic, tid);
        CP_COMMIT();

#pragma unroll 1
        for (int d = 0; d < DKS_; ++d) {
            CP_WAIT0();        // A(d) (and X on d=0) landed for this thread
            __syncthreads();   // visible to all; all done with buf (d+1)&1

            if (d < DKS_ - 1) {            // overlap A(d+1) copy with compute(d)
                stage_A(A0, d + 1, o0, ic, tid);
                CP_COMMIT();
            }

            const uint32_t Ab = A0 + (uint32_t)(d & 1) * A_BUF;
#pragma unroll
            for (int kk = 0; kk < 2; ++kk) {
                // A fragments for this kk (keeps live regs low)
                uint32_t ah[2][4], al[2][4];
#pragma unroll
                for (int mi = 0; mi < 2; ++mi) {
                    uint32_t ad = Ab + (wm * 32 + mi * 16 + a_r) * ROWB + kk * 32 + a_c;
                    ldmx4(ah[mi], ad);
                    ldmx4(al[mi], ad + A_TS);
                }
#pragma unroll
                for (int p = 0; p < 4; ++p) {
                    uint32_t bh[4], bl[4];
                    uint32_t bd = X0 + (wn * 64 + d + p * 16 + b_r) * ROWB
                                + kk * 32 + b_c;
                    ldmx4(bh, bd);
                    ldmx4(bl, bd + X_TS);
#pragma unroll
                    for (int mi = 0; mi < 2; ++mi)
#pragma unroll
                        for (int nn = 0; nn < 2; ++nn) {
                            MMA(acc[mi][p * 2 + nn], ah[mi], bh[2 * nn], bh[2 * nn + 1]);
                            MMA(acc[mi][p * 2 + nn], ah[mi], bl[2 * nn], bl[2 * nn + 1]);
                            MMA(acc[mi][p * 2 + nn], al[mi], bh[2 * nn], bh[2 * nn + 1]);
                        }
                }
            }
        }
    }

    // ---- epilogue: add bias, store float2 ----
    const int g = lane >> 2, tg = lane & 3;
#pragma unroll
    for (int mi = 0; mi < 2; ++mi) {
        int o1 = o0 + wm * 32 + mi * 16 + g;
        float bv1 = bias[o1], bv2 = bias[o1 + 8];
        float* r1 = out + ((size_t)(b * O_ + o1)) * T_ + t0 + wn * 64 + tg * 2;
        float* r2 = r1 + 8 * T_;
#pragma unroll
        for (int nf = 0; nf < 8; ++nf) {
            float2 v1 = make_float2(acc[mi][nf][0] + bv1, acc[mi][nf][1] + bv1);
            float2 v2 = make_float2(acc[mi][nf][2] + bv2, acc[mi][nf][3] + bv2);
            *(float2*)(r1 + nf * 8) = v1;
            *(float2*)(r2 + nf * 8) = v2;
        }
    }
}

// ---------------------------------------------------------------------------
// Launch
// ---------------------------------------------------------------------------
extern "C" void kernel_launch(void* const* d_in, const int* in_sizes, int n_in,
                              void* d_out, int out_size) {
    const float* x      = (const float*)d_in[0];
    const float* weight = (const float*)d_in[1];
    const float* P      = (const float*)d_in[2];
    const float* bias   = (const float*)d_in[3];
    float* out          = (float*)d_out;

    build_k2<<<256, 256>>>(weight, P);
    xsplit<<<dim3(T_ / 32, C_ / 32, B_), 256>>>(x);
    zpad<<<64, 1024>>>();

    cudaFuncSetAttribute(conv_mma, cudaFuncAttributeMaxDynamicSharedMemorySize, DSMEM);
    conv_mma<<<dim3(64, 2), 512, DSMEM>>>(bias, out);
}

// round 7
// speedup vs baseline: 7.3974x; 3.7708x over previous
#include <cuda_runtime.h>
#include <cuda_bf16.h>
#include <cstdint>

// ---------------------------------------------------------------------------
// Dcls1d via mma.sync (HMMA) bf16 split-GEMM with ACTIVE-d COMPACTION.
//   out[b,o,t] = bias[o] + sum_{d,i} K2[d,o,i] * x[b,i,t+d-16]
//   P ~ clip(0.5*N(0,1)) -> most K2 d-slices are EXACTLY zero; build a
//   per-o-tile active-d list on device and run dense GEMM only on those.
//   fp32 emulated as bf16 hi+lo, 3 products (hh, hl, lh), fp32 accum.
// ---------------------------------------------------------------------------

#define B_   8
#define C_   256
#define T_   2048
#define O_   256
#define DKS_ 33
#define KC_  16
#define TP_  2080   // 16 + 2048 + 16 padded time rows

__device__ __nv_bfloat16 g_Khi[DKS_ * O_ * C_];   // [d][o][i]
__device__ __nv_bfloat16 g_Klo[DKS_ * O_ * C_];
__device__ __nv_bfloat16 g_Xhi[B_ * TP_ * C_];    // [b][t+16][i]
__device__ __nv_bfloat16 g_Xlo[B_ * TP_ * C_];

__device__ unsigned long long g_mask[2];          // nonzero-slice mask per o-tile
__device__ int g_nact[2];
__device__ int g_active[2][DKS_];

// ---- PTX helpers -----------------------------------------------------------
__device__ __forceinline__ uint32_t smem_u32(const void* p) {
    uint32_t a;
    asm("{ .reg .u64 t; cvta.to.shared.u64 t, %1; cvt.u32.u64 %0, t; }"
        : "=r"(a) : "l"(p));
    return a;
}
__device__ __forceinline__ void cpa16(uint32_t dst, const void* src) {
    asm volatile("cp.async.ca.shared.global [%0], [%1], 16;" :: "r"(dst), "l"(src));
}
#define CP_COMMIT() asm volatile("cp.async.commit_group;" ::: "memory")
#define CP_WAIT0()  asm volatile("cp.async.wait_group 0;" ::: "memory")

__device__ __forceinline__ void ldmx4(uint32_t* r, uint32_t addr) {
    asm volatile("ldmatrix.sync.aligned.m8n8.x4.shared.b16 {%0,%1,%2,%3}, [%4];"
                 : "=r"(r[0]), "=r"(r[1]), "=r"(r[2]), "=r"(r[3]) : "r"(addr));
}
#define MMA(dv, a, b0v, b1v)                                                   \
    asm volatile("mma.sync.aligned.m16n8k16.row.col.f32.bf16.bf16.f32 "        \
                 "{%0,%1,%2,%3},{%4,%5,%6,%7},{%8,%9},{%0,%1,%2,%3};"          \
                 : "+f"((dv)[0]), "+f"((dv)[1]), "+f"((dv)[2]), "+f"((dv)[3])  \
                 : "r"((a)[0]), "r"((a)[1]), "r"((a)[2]), "r"((a)[3]),         \
                   "r"(b0v), "r"(b1v))

// ---------------------------------------------------------------------------
// Prep 0: reset masks (graph replays must be deterministic).
// ---------------------------------------------------------------------------
__global__ void init_mask() {
    if (threadIdx.x < 2) g_mask[threadIdx.x] = 0ull;
}

// ---------------------------------------------------------------------------
// Prep 1: build K2 (bf16 hi/lo), layout [d][o][i]; accumulate nonzero masks.
// ---------------------------------------------------------------------------
__global__ void build_k2(const float* __restrict__ w, const float* __restrict__ P) {
    int oi = blockIdx.x * 256 + threadIdx.x;      // one o per block
    int ig = oi & 255;
    float acc[DKS_];
#pragma unroll
    for (int d = 0; d < DKS_; ++d) acc[d] = 0.f;

    const float* Prow  = P + (size_t)oi * KC_;
    const float* P0row = P + (size_t)ig * KC_;    // out-channel 0 (frac source)
    const float* Wrow  = w + (size_t)oi * KC_;
#pragma unroll
    for (int k = 0; k < KC_; ++k) {
        float pp  = Prow[k] + 16.f;
        int   p   = (int)floorf(pp);
        float pp0 = P0row[k] + 16.f;
        float fr  = pp0 - floorf(pp0);
        float wv  = Wrow[k];
        if (p >= 0 && p < DKS_)         acc[p]     += wv * (1.f - fr);
        if (p + 1 >= 0 && p + 1 < DKS_) acc[p + 1] += wv * fr;
    }
    unsigned long long bits = 0ull;
#pragma unroll
    for (int d = 0; d < DKS_; ++d) {
        float v = acc[d];
        if (v != 0.f) bits |= 1ull << d;
        __nv_bfloat16 h = __float2bfloat16(v);
        __nv_bfloat16 l = __float2bfloat16(v - __bfloat162float(h));
        size_t idx = (size_t)(d * O_ + (oi >> 8)) * C_ + ig;
        g_Khi[idx] = h;
        g_Klo[idx] = l;
    }
    // warp-reduce OR, one atomic per warp
#pragma unroll
    for (int s = 16; s > 0; s >>= 1) {
        bits |= __shfl_xor_sync(0xffffffffu, bits, s);
    }
    if ((threadIdx.x & 31) == 0)
        atomicOr(&g_mask[oi >> 15], bits);        // tile = o >> 7
}

// Prep 1b: compact mask -> active list per tile.
__global__ void compact_mask() {
    int tile = threadIdx.x;
    if (tile < 2) {
        unsigned long long m = g_mask[tile];
        int n = 0;
        for (int d = 0; d < DKS_; ++d)
            if (m & (1ull << d)) g_active[tile][n++] = d;
        g_nact[tile] = n;
    }
}

// ---------------------------------------------------------------------------
// Prep 2: transpose+split x -> g_Xhi/lo [b][t+16][i]
// ---------------------------------------------------------------------------
__global__ void xsplit(const float* __restrict__ x) {
    __shared__ float sm[32][33];
    int t0 = blockIdx.x * 32, i0 = blockIdx.y * 32, b = blockIdx.z;
    int tl = threadIdx.x & 31, th = threadIdx.x >> 5;
#pragma unroll
    for (int k = 0; k < 4; ++k) {
        int i = i0 + th + k * 8;
        sm[th + k * 8][tl] = x[((size_t)b * C_ + i) * T_ + t0 + tl];
    }
    __syncthreads();
#pragma unroll
    for (int k = 0; k < 4; ++k) {
        int t = t0 + th + k * 8;
        float v = sm[tl][th + k * 8];
        __nv_bfloat16 h = __float2bfloat16(v);
        __nv_bfloat16 l = __float2bfloat16(v - __bfloat162float(h));
        size_t idx = ((size_t)b * TP_ + t + 16) * C_ + i0 + tl;
        g_Xhi[idx] = h;
        g_Xlo[idx] = l;
    }
}

__global__ void zpad() {
    int idx = blockIdx.x * 1024 + threadIdx.x;     // 65536 total
    int b = idx >> 13, r = (idx >> 8) & 31, i = idx & 255;
    int row = (r < 16) ? r : (TP_ - 32 + r);
    size_t o = ((size_t)b * TP_ + row) * C_ + i;
    g_Xhi[o] = __float2bfloat16(0.f);
    g_Xlo[o] = __float2bfloat16(0.f);
}

// ---------------------------------------------------------------------------
// Main GEMM kernel.
// Block: 128 o x 256 t, 512 threads (16 warps: 4 M x 4 N, warp = 32 o x 64 t).
// Loops only over ACTIVE d values. smem rows 80B stride (conflict-free LDSM).
// ---------------------------------------------------------------------------
#define ROWB   80u
#define A_TS   10240u      // one A tensor (128*80)
#define A_BUF  20480u      // hi+lo pair
#define X_OFF  40960u
#define X_TS   23040u      // one X tensor (288*80)
#define DSMEM  (40960u + 2u * 23040u + 256u)

__device__ __forceinline__ void stage_A(uint32_t A0, int d, int slot,
                                        int o0, int ic, int tid) {
    uint32_t Ab = A0 + (uint32_t)slot * A_BUF;
#pragma unroll
    for (int k = 0; k < 2; ++k) {
        int idx = tid + k * 512;
        int tn  = idx >> 9;
        int r   = (idx >> 2) & 127;
        int c   = idx & 3;
        const __nv_bfloat16* src = (tn ? g_Klo : g_Khi)
            + ((size_t)(d * 256 + o0 + r) * 256 + ic * 32 + c * 8);
        cpa16(Ab + (uint32_t)tn * A_TS + r * ROWB + c * 16, src);
    }
}

__global__ __launch_bounds__(512, 1)
void conv_mma(const float* __restrict__ bias, float* __restrict__ out) {
    extern __shared__ char dsm_raw[];
    uint32_t raw  = smem_u32(dsm_raw);
    uint32_t base = (raw + 127u) & ~127u;

    const int tid  = threadIdx.x;
    const int lane = tid & 31, w = tid >> 5;
    const int wm = w & 3, wn = w >> 2;            // 4 M-warps x 4 N-warps
    const int b  = blockIdx.x >> 3;
    const int t0 = (blockIdx.x & 7) * 256;
    const int tile = blockIdx.y;
    const int o0 = tile * 128;

    const uint32_t A0 = base;
    const uint32_t X0 = base + X_OFF;

    float acc[2][8][4];                           // [mi][p*2+nn][quad]
#pragma unroll
    for (int mi = 0; mi < 2; ++mi)
#pragma unroll
        for (int nf = 0; nf < 8; ++nf)
#pragma unroll
            for (int q = 0; q < 4; ++q) acc[mi][nf][q] = 0.f;

    // ldmatrix per-lane row/col offsets
    const uint32_t a_r = (lane & 7) + 8 * ((lane >> 3) & 1);
    const uint32_t a_c = (uint32_t)(lane >> 4) * 16;
    const uint32_t b_r = (lane & 7) + 8 * (lane >> 4);
    const uint32_t b_c = (uint32_t)((lane >> 3) & 1) * 16;

    const int n_act = g_nact[tile];
    const int* act  = g_active[tile];

    if (n_act > 0) {
        for (int ic = 0; ic < 8; ++ic) {
            __syncthreads();    // protect X & A buffers vs previous ic's compute
            // ---- stage X tile (288 rows x 32 i, hi+lo): 2304 x 16B chunks ----
#pragma unroll
            for (int k = 0; k < 5; ++k) {
                int idx = tid + k * 512;
                if (idx < 2304) {
                    int tn  = idx >= 1152;
                    int r   = (idx - tn * 1152) >> 2;
                    int c   = idx & 3;
                    const __nv_bfloat16* src = (tn ? g_Xlo : g_Xhi)
                        + ((size_t)(b * TP_ + t0 + r) * 256 + ic * 32 + c * 8);
                    cpa16(X0 + (uint32_t)tn * X_TS + r * ROWB + c * 16, src);
                }
            }
            // ---- stage A(act[0]) into buf0 ----
            stage_A(A0, act[0], 0, o0, ic, tid);
            CP_COMMIT();

#pragma unroll 1
            for (int j = 0; j < n_act; ++j) {
                const int d = act[j];
                CP_WAIT0();        // A(j) (and X on j=0) landed for this thread
                __syncthreads();   // visible to all; all done with buf (j+1)&1

                if (j < n_act - 1) {   // overlap A(j+1) copy with compute(j)
                    stage_A(A0, act[j + 1], (j + 1) & 1, o0, ic, tid);
                    CP_COMMIT();
                }

                const uint32_t Ab = A0 + (uint32_t)(j & 1) * A_BUF;
#pragma unroll
                for (int kk = 0; kk < 2; ++kk) {
                    uint32_t ah[2][4], al[2][4];
#pragma unroll
                    for (int mi = 0; mi < 2; ++mi) {
                        uint32_t ad = Ab + (wm * 32 + mi * 16 + a_r) * ROWB
                                    + kk * 32 + a_c;
                        ldmx4(ah[mi], ad);
                        ldmx4(al[mi], ad + A_TS);
                    }
#pragma unroll
                    for (int p = 0; p < 4; ++p) {
                        uint32_t bh[4], bl[4];
                        uint32_t bd = X0 + (wn * 64 + d + p * 16 + b_r) * ROWB
                                    + kk * 32 + b_c;
                        ldmx4(bh, bd);
                        ldmx4(bl, bd + X_TS);
#pragma unroll
                        for (int mi = 0; mi < 2; ++mi)
#pragma unroll
                            for (int nn = 0; nn < 2; ++nn) {
                                MMA(acc[mi][p * 2 + nn], ah[mi], bh[2 * nn], bh[2 * nn + 1]);
                                MMA(acc[mi][p * 2 + nn], ah[mi], bl[2 * nn], bl[2 * nn + 1]);
                                MMA(acc[mi][p * 2 + nn], al[mi], bh[2 * nn], bh[2 * nn + 1]);
                            }
                    }
                }
            }
        }
    }

    // ---- epilogue: add bias, store float2 ----
    const int g = lane >> 2, tg = lane & 3;
#pragma unroll
    for (int mi = 0; mi < 2; ++mi) {
        int o1 = o0 + wm * 32 + mi * 16 + g;
        float bv1 = bias[o1], bv2 = bias[o1 + 8];
        float* r1 = out + ((size_t)(b * O_ + o1)) * T_ + t0 + wn * 64 + tg * 2;
        float* r2 = r1 + 8 * T_;
#pragma unroll
        for (int nf = 0; nf < 8; ++nf) {
            float2 v1 = make_float2(acc[mi][nf][0] + bv1, acc[mi][nf][1] + bv1);
            float2 v2 = make_float2(acc[mi][nf][2] + bv2, acc[mi][nf][3] + bv2);
            *(float2*)(r1 + nf * 8) = v1;
            *(float2*)(r2 + nf * 8) = v2;
        }
    }
}

// ---------------------------------------------------------------------------
// Launch
// ---------------------------------------------------------------------------
extern "C" void kernel_launch(void* const* d_in, const int* in_sizes, int n_in,
                              void* d_out, int out_size) {
    const float* x      = (const float*)d_in[0];
    const float* weight = (const float*)d_in[1];
    const float* P      = (const float*)d_in[2];
    const float* bias   = (const float*)d_in[3];
    float* out          = (float*)d_out;

    init_mask<<<1, 32>>>();
    build_k2<<<256, 256>>>(weight, P);
    compact_mask<<<1, 32>>>();
    xsplit<<<dim3(T_ / 32, C_ / 32, B_), 256>>>(x);
    zpad<<<64, 1024>>>();

    cudaFuncSetAttribute(conv_mma, cudaFuncAttributeMaxDynamicSharedMemorySize, DSMEM);
    conv_mma<<<dim3(64, 2), 512, DSMEM>>>(bias, out);
}

// round 8
// speedup vs baseline: 7.9704x; 1.0775x over previous
#include <cuda_runtime.h>
#include <cuda_bf16.h>
#include <cstdint>

// ---------------------------------------------------------------------------
// Dcls1d via mma.sync (HMMA) bf16 split-GEMM with ACTIVE-d COMPACTION.
//   out[b,o,t] = bias[o] + sum_{d,i} K2[d,o,i] * x[b,i,t+d-16]
//   P ~ clip(0.5*N(0,1)) -> most K2 d-slices are EXACTLY zero; per-o-tile
//   nonzero mask built in build_k2, compacted in conv_mma prologue.
//   fp32 emulated as bf16 hi+lo, 3 products (hh, hl, lh), fp32 accum.
// R8: ic-chunk 64 (4 chunks, half the sync points), 3 launches total.
// ---------------------------------------------------------------------------

#define B_   8
#define C_   256
#define T_   2048
#define O_   256
#define DKS_ 33
#define KC_  16
#define TP_  2080   // 16 + 2048 + 16 padded time rows

__device__ __nv_bfloat16 g_Khi[DKS_ * O_ * C_];   // [d][o][i]
__device__ __nv_bfloat16 g_Klo[DKS_ * O_ * C_];
__device__ __nv_bfloat16 g_Xhi[B_ * TP_ * C_];    // [b][t+16][i]
__device__ __nv_bfloat16 g_Xlo[B_ * TP_ * C_];
__device__ unsigned long long g_mask[2];          // nonzero-slice mask per o-tile

// ---- PTX helpers -----------------------------------------------------------
__device__ __forceinline__ uint32_t smem_u32(const void* p) {
    uint32_t a;
    asm("{ .reg .u64 t; cvta.to.shared.u64 t, %1; cvt.u32.u64 %0, t; }"
        : "=r"(a) : "l"(p));
    return a;
}
__device__ __forceinline__ void cpa16(uint32_t dst, const void* src) {
    asm volatile("cp.async.ca.shared.global [%0], [%1], 16;" :: "r"(dst), "l"(src));
}
#define CP_COMMIT() asm volatile("cp.async.commit_group;" ::: "memory")
#define CP_WAIT0()  asm volatile("cp.async.wait_group 0;" ::: "memory")

__device__ __forceinline__ void ldmx4(uint32_t* r, uint32_t addr) {
    asm volatile("ldmatrix.sync.aligned.m8n8.x4.shared.b16 {%0,%1,%2,%3}, [%4];"
                 : "=r"(r[0]), "=r"(r[1]), "=r"(r[2]), "=r"(r[3]) : "r"(addr));
}
#define MMA(dv, a, b0v, b1v)                                                   \
    asm volatile("mma.sync.aligned.m16n8k16.row.col.f32.bf16.bf16.f32 "        \
                 "{%0,%1,%2,%3},{%4,%5,%6,%7},{%8,%9},{%0,%1,%2,%3};"          \
                 : "+f"((dv)[0]), "+f"((dv)[1]), "+f"((dv)[2]), "+f"((dv)[3])  \
                 : "r"((a)[0]), "r"((a)[1]), "r"((a)[2]), "r"((a)[3]),         \
                   "r"(b0v), "r"(b1v))

// ---------------------------------------------------------------------------
// Kernel A: transpose+split x -> g_Xhi/lo [b][t+16][i]; zero pads; reset mask.
// ---------------------------------------------------------------------------
__global__ void xsplit(const float* __restrict__ x) {
    __shared__ float sm[32][33];
    int t0 = blockIdx.x * 32, i0 = blockIdx.y * 32, b = blockIdx.z;
    int tid = threadIdx.x;
    int tl = tid & 31, th = tid >> 5;

    if (blockIdx.x == 0 && blockIdx.y == 0 && blockIdx.z == 0 && tid < 2)
        g_mask[tid] = 0ull;   // stream order: completes before build_k2 runs

    // zero pads (first/last 16 rows of this batch, this i-stripe)
    if (blockIdx.x == 0) {
#pragma unroll
        for (int k = 0; k < 2; ++k) {
            int e = tid + k * 256;            // 512 = 16 rows x 32 cols
            int r = e >> 5, cc = e & 31;
            size_t o1 = ((size_t)b * TP_ + r) * C_ + i0 + cc;
            size_t o2 = ((size_t)b * TP_ + (TP_ - 16 + r)) * C_ + i0 + cc;
            g_Xhi[o1] = __float2bfloat16(0.f);
            g_Xlo[o1] = __float2bfloat16(0.f);
            g_Xhi[o2] = __float2bfloat16(0.f);
            g_Xlo[o2] = __float2bfloat16(0.f);
        }
    }

#pragma unroll
    for (int k = 0; k < 4; ++k) {
        int i = i0 + th + k * 8;
        sm[th + k * 8][tl] = x[((size_t)b * C_ + i) * T_ + t0 + tl];
    }
    __syncthreads();
#pragma unroll
    for (int k = 0; k < 4; ++k) {
        int t = t0 + th + k * 8;
        float v = sm[tl][th + k * 8];
        __nv_bfloat16 h = __float2bfloat16(v);
        __nv_bfloat16 l = __float2bfloat16(v - __bfloat162float(h));
        size_t idx = ((size_t)b * TP_ + t + 16) * C_ + i0 + tl;
        g_Xhi[idx] = h;
        g_Xlo[idx] = l;
    }
}

// ---------------------------------------------------------------------------
// Kernel B: build K2 (bf16 hi/lo), layout [d][o][i]; accumulate nonzero masks.
// ---------------------------------------------------------------------------
__global__ void build_k2(const float* __restrict__ w, const float* __restrict__ P) {
    int oi = blockIdx.x * 256 + threadIdx.x;
    int ig = oi & 255;
    float acc[DKS_];
#pragma unroll
    for (int d = 0; d < DKS_; ++d) acc[d] = 0.f;

    const float* Prow  = P + (size_t)oi * KC_;
    const float* P0row = P + (size_t)ig * KC_;    // out-channel 0 (frac source)
    const float* Wrow  = w + (size_t)oi * KC_;
#pragma unroll
    for (int k = 0; k < KC_; ++k) {
        float pp  = Prow[k] + 16.f;
        int   p   = (int)floorf(pp);
        float pp0 = P0row[k] + 16.f;
        float fr  = pp0 - floorf(pp0);
        float wv  = Wrow[k];
        if (p >= 0 && p < DKS_)         acc[p]     += wv * (1.f - fr);
        if (p + 1 >= 0 && p + 1 < DKS_) acc[p + 1] += wv * fr;
    }
    unsigned long long bits = 0ull;
#pragma unroll
    for (int d = 0; d < DKS_; ++d) {
        float v = acc[d];
        if (v != 0.f) bits |= 1ull << d;
        __nv_bfloat16 h = __float2bfloat16(v);
        __nv_bfloat16 l = __float2bfloat16(v - __bfloat162float(h));
        size_t idx = (size_t)(d * O_ + (oi >> 8)) * C_ + ig;
        g_Khi[idx] = h;
        g_Klo[idx] = l;
    }
#pragma unroll
    for (int s = 16; s > 0; s >>= 1)
        bits |= __shfl_xor_sync(0xffffffffu, bits, s);
    if ((threadIdx.x & 31) == 0)
        atomicOr(&g_mask[oi >> 15], bits);        // tile = o >> 7
}

// ---------------------------------------------------------------------------
// Kernel C: the GEMM.
// Block: 128 o x 256 t, 512 threads (16 warps: 4 M x 4 N, warp = 32 o x 64 t).
// ic-chunk = 64 i (4 chunks). smem rows 144B stride (conflict-free LDSM).
//   A (K2[d] tile): 128 x 64 i, hi+lo, double buffered: 2 x 36864 B
//   X tile:         288 x 64 i, hi+lo:                   82944 B
// ---------------------------------------------------------------------------
#define ROWB   144u
#define A_TS   18432u      // one A tensor (128*144)
#define A_BUF  36864u      // hi+lo pair
#define X_OFF  73728u
#define X_TS   41472u      // one X tensor (288*144)
#define DSMEM  (73728u + 2u * 41472u + 256u)

__device__ __forceinline__ void stage_A(uint32_t A0, int d, int slot,
                                        int o0, int ic, int tid) {
    uint32_t Ab = A0 + (uint32_t)slot * A_BUF;
#pragma unroll
    for (int k = 0; k < 4; ++k) {
        int idx = tid + k * 512;                 // 2048 chunks
        int tn  = idx >> 10;
        int r   = (idx >> 3) & 127;
        int c   = idx & 7;
        const __nv_bfloat16* src = (tn ? g_Klo : g_Khi)
            + ((size_t)(d * 256 + o0 + r) * 256 + ic * 64 + c * 8);
        cpa16(Ab + (uint32_t)tn * A_TS + r * ROWB + c * 16, src);
    }
}

__global__ __launch_bounds__(512, 1)
void conv_mma(const float* __restrict__ bias, float* __restrict__ out) {
    extern __shared__ char dsm_raw[];
    uint32_t raw  = smem_u32(dsm_raw);
    uint32_t base = (raw + 127u) & ~127u;

    __shared__ int s_act[DKS_];
    __shared__ int s_n;

    const int tid  = threadIdx.x;
    const int lane = tid & 31, w = tid >> 5;
    const int wm = w & 3, wn = w >> 2;            // 4 M-warps x 4 N-warps
    const int b  = blockIdx.x >> 3;
    const int t0 = (blockIdx.x & 7) * 256;
    const int tile = blockIdx.y;
    const int o0 = tile * 128;

    // compact mask -> active list (prologue)
    if (tid == 0) {
        unsigned long long m = g_mask[tile];
        int n = 0;
        for (int d = 0; d < DKS_; ++d)
            if (m & (1ull << d)) s_act[n++] = d;
        s_n = n;
    }
    __syncthreads();
    const int n_act = s_n;

    const uint32_t A0 = base;
    const uint32_t X0 = base + X_OFF;

    float acc[2][8][4];                           // [mi][p*2+nn][quad]
#pragma unroll
    for (int mi = 0; mi < 2; ++mi)
#pragma unroll
        for (int nf = 0; nf < 8; ++nf)
#pragma unroll
            for (int q = 0; q < 4; ++q) acc[mi][nf][q] = 0.f;

    // ldmatrix per-lane row/col offsets
    const uint32_t a_r = (lane & 7) + 8 * ((lane >> 3) & 1);
    const uint32_t a_c = (uint32_t)(lane >> 4) * 16;
    const uint32_t b_r = (lane & 7) + 8 * (lane >> 4);
    const uint32_t b_c = (uint32_t)((lane >> 3) & 1) * 16;

    if (n_act > 0) {
        for (int ic = 0; ic < 4; ++ic) {
            __syncthreads();    // protect X & A buffers vs previous ic's compute
            // ---- stage X tile (288 rows x 64 i, hi+lo): 4608 x 16B chunks ----
#pragma unroll
            for (int k = 0; k < 9; ++k) {
                int idx = tid + k * 512;
                int tn  = idx >= 2304;
                int r   = (idx - tn * 2304) >> 3;
                int c   = idx & 7;
                const __nv_bfloat16* src = (tn ? g_Xlo : g_Xhi)
                    + ((size_t)(b * TP_ + t0 + r) * 256 + ic * 64 + c * 8);
                cpa16(X0 + (uint32_t)tn * X_TS + r * ROWB + c * 16, src);
            }
            // ---- stage A(act[0]) into buf0 ----
            stage_A(A0, s_act[0], 0, o0, ic, tid);
            CP_COMMIT();

#pragma unroll 1
            for (int j = 0; j < n_act; ++j) {
                const int d = s_act[j];
                CP_WAIT0();        // A(j) (and X on j=0) landed for this thread
                __syncthreads();   // visible to all; all done with buf (j+1)&1

                if (j < n_act - 1) {   // overlap A(j+1) copy with compute(j)
                    stage_A(A0, s_act[j + 1], (j + 1) & 1, o0, ic, tid);
                    CP_COMMIT();
                }

                const uint32_t Ab = A0 + (uint32_t)(j & 1) * A_BUF;
#pragma unroll
                for (int kk = 0; kk < 4; ++kk) {
                    uint32_t ah[2][4], al[2][4];
#pragma unroll
                    for (int mi = 0; mi < 2; ++mi) {
                        uint32_t ad = Ab + (wm * 32 + mi * 16 + a_r) * ROWB
                                    + kk * 32 + a_c;
                        ldmx4(ah[mi], ad);
                        ldmx4(al[mi], ad + A_TS);
                    }
#pragma unroll
                    for (int p = 0; p < 4; ++p) {
                        uint32_t bh[4], bl[4];
                        uint32_t bd = X0 + (wn * 64 + d + p * 16 + b_r) * ROWB
                                    + kk * 32 + b_c;
                        ldmx4(bh, bd);
                        ldmx4(bl, bd + X_TS);
#pragma unroll
                        for (int mi = 0; mi < 2; ++mi)
#pragma unroll
                            for (int nn = 0; nn < 2; ++nn) {
                                MMA(acc[mi][p * 2 + nn], ah[mi], bh[2 * nn], bh[2 * nn + 1]);
                                MMA(acc[mi][p * 2 + nn], ah[mi], bl[2 * nn], bl[2 * nn + 1]);
                                MMA(acc[mi][p * 2 + nn], al[mi], bh[2 * nn], bh[2 * nn + 1]);
                            }
                    }
                }
            }
        }
    }

    // ---- epilogue: add bias, store float2 ----
    const int g = lane >> 2, tg = lane & 3;
#pragma unroll
    for (int mi = 0; mi < 2; ++mi) {
        int o1 = o0 + wm * 32 + mi * 16 + g;
        float bv1 = bias[o1], bv2 = bias[o1 + 8];
        float* r1 = out + ((size_t)(b * O_ + o1)) * T_ + t0 + wn * 64 + tg * 2;
        float* r2 = r1 + 8 * T_;
#pragma unroll
        for (int nf = 0; nf < 8; ++nf) {
            float2 v1 = make_float2(acc[mi][nf][0] + bv1, acc[mi][nf][1] + bv1);
            float2 v2 = make_float2(acc[mi][nf][2] + bv2, acc[mi][nf][3] + bv2);
            *(float2*)(r1 + nf * 8) = v1;
            *(float2*)(r2 + nf * 8) = v2;
        }
    }
}

// ---------------------------------------------------------------------------
// Launch (3 kernels)
// ---------------------------------------------------------------------------
extern "C" void kernel_launch(void* const* d_in, const int* in_sizes, int n_in,
                              void* d_out, int out_size) {
    const float* x      = (const float*)d_in[0];
    const float* weight = (const float*)d_in[1];
    const float* P      = (const float*)d_in[2];
    const float* bias   = (const float*)d_in[3];
    float* out          = (float*)d_out;

    xsplit<<<dim3(T_ / 32, C_ / 32, B_), 256>>>(x);
    build_k2<<<256, 256>>>(weight, P);

    cudaFuncSetAttribute(conv_mma, cudaFuncAttributeMaxDynamicSharedMemorySize, DSMEM);
    conv_mma<<<dim3(64, 2), 512, DSMEM>>>(bias, out);
}